// round 3
// baseline (speedup 1.0000x reference)
#include <cuda_runtime.h>
#include <cstdint>

// ---------------- constants ----------------
#define IN_DIM 128
#define HID 128
#define H2 256
#define MAX_ATOMS 500032   // 500000 padded to multiple of 64
#define MAX_GRAPHS 16384

// ---------------- scratch (device globals; no allocs allowed) ----------------
__device__ float g_S[(size_t)MAX_ATOMS * IN_DIM];      // segment_sum(node_hidden[src]+edge_hidden, dst)
__device__ float g_deg[MAX_ATOMS];                      // in-degree per atom
__device__ float g_gsum_nh[MAX_GRAPHS * HID];           // per-graph sum of node_hidden
__device__ float g_gsum_hn[MAX_GRAPHS * HID];           // per-graph sum of h_n
__device__ float g_cnt[MAX_GRAPHS];                     // atoms per graph
__device__ float g_H1[(size_t)MAX_ATOMS * H2];          // relu(first MLP layer)
__device__ float g_WW1[IN_DIM * H2];                    // atom_w @ nmlp_w1
__device__ float g_bvec1[H2];                           // 2 * atom_b @ nmlp_w1

// ---------------- f32x2 packed-FMA helpers ----------------
__device__ __forceinline__ unsigned long long pack2(float lo, float hi) {
    unsigned long long r;
    asm("mov.b64 %0, {%1, %2};" : "=l"(r) : "f"(lo), "f"(hi));
    return r;
}
__device__ __forceinline__ float2 unpack2(unsigned long long v) {
    float2 r;
    asm("mov.b64 {%0, %1}, %2;" : "=f"(r.x), "=f"(r.y) : "l"(v));
    return r;
}
__device__ __forceinline__ void fma2(unsigned long long& d, unsigned long long a, unsigned long long b) {
    asm("fma.rn.f32x2 %0, %1, %2, %0;" : "+l"(d) : "l"(a), "l"(b));
}
__device__ __forceinline__ void red_add_v4(float* p, float4 v) {
    asm volatile("red.global.add.v4.f32 [%0], {%1,%2,%3,%4};"
                 :: "l"(p), "f"(v.x), "f"(v.y), "f"(v.z), "f"(v.w) : "memory");
}
__device__ __forceinline__ void red_add_v2(float* p, float a, float b) {
    asm volatile("red.global.add.v2.f32 [%0], {%1,%2};"
                 :: "l"(p), "f"(a), "f"(b) : "memory");
}

// ---------------- zero scratch ----------------
__global__ void zero_kernel() {
    long i = (long)blockIdx.x * blockDim.x + threadIdx.x;  // float4 index
    float4 z = make_float4(0.f, 0.f, 0.f, 0.f);
    const long nS = (long)MAX_ATOMS * IN_DIM / 4;
    if (i < nS) reinterpret_cast<float4*>(g_S)[i] = z;
    if (i < MAX_ATOMS / 4) reinterpret_cast<float4*>(g_deg)[i] = z;
    if (i < (long)MAX_GRAPHS * HID / 4) {
        reinterpret_cast<float4*>(g_gsum_nh)[i] = z;
        reinterpret_cast<float4*>(g_gsum_hn)[i] = z;
    }
    if (i < MAX_GRAPHS / 4) reinterpret_cast<float4*>(g_cnt)[i] = z;
}

// ---------------- WW1 = atom_w @ nmlp_w1 ; bvec1 = 2 * atom_b @ nmlp_w1 ----------------
__global__ __launch_bounds__(256) void prep_kernel(const float* __restrict__ atom_w,
                                                   const float* __restrict__ atom_b,
                                                   const float* __restrict__ w1) {
    int j = threadIdx.x;   // 0..255
    int i = blockIdx.x;    // 0..128
    if (i < IN_DIM) {
        float acc = 0.f;
        #pragma unroll 8
        for (int k = 0; k < IN_DIM; k++)
            acc += __ldg(atom_w + i * IN_DIM + k) * __ldg(w1 + k * H2 + j);
        g_WW1[i * H2 + j] = acc;
    } else {
        float acc = 0.f;
        #pragma unroll 8
        for (int k = 0; k < IN_DIM; k++)
            acc += __ldg(atom_b + k) * __ldg(w1 + k * H2 + j);
        g_bvec1[j] = 2.f * acc;
    }
}

// ---------------- scatter bonds: S[dst] += node_hidden[src] + edge_hidden ----------------
__global__ __launch_bounds__(256) void scatter_kernel(const float4* __restrict__ nh,
                                                      const float4* __restrict__ eh,
                                                      const int* __restrict__ src,
                                                      const int* __restrict__ dst,
                                                      int nBonds) {
    int t = blockIdx.x * 256 + threadIdx.x;
    int e = t >> 5, lane = t & 31;
    if (e >= nBonds) return;
    int s = __ldg(src + e), d = __ldg(dst + e);
    float4 a = __ldg(nh + (long)s * 32 + lane);
    float4 b = __ldg(eh + (long)e * 32 + lane);
    float4 v = make_float4(a.x + b.x, a.y + b.y, a.z + b.z, a.w + b.w);
    red_add_v4(g_S + (long)d * IN_DIM + lane * 4, v);
    if (lane == 0) atomicAdd(g_deg + d, 1.0f);
}

// ---------------- pool node_hidden per graph (sorted ids; atomics fine) ----------------
__global__ __launch_bounds__(256) void pool_nodes_kernel(const float4* __restrict__ nh,
                                                         const int* __restrict__ gid,
                                                         int nAtoms) {
    int t = blockIdx.x * 256 + threadIdx.x;
    int a = t >> 5, lane = t & 31;
    if (a >= nAtoms) return;
    int g = __ldg(gid + a);
    float4 v = __ldg(nh + (long)a * 32 + lane);
    red_add_v4(g_gsum_nh + (long)g * HID + lane * 4, v);
    if (lane == 0) atomicAdd(g_cnt + g, 1.0f);
}

// ---------------- GEMM1: H1 = relu(S @ WW1 + b1 + deg * bvec1)  [M,128]x[128,256] ----------------
// block: 64 rows x 256 cols, 256 threads, per-thread 8 rows x 4 col-pairs, f32x2 FMAs
__global__ __launch_bounds__(256) void gemm1_kernel(const float* __restrict__ b1) {
    extern __shared__ float sm[];
    float* Bs = sm;                  // [128][256]
    float* As = sm + IN_DIM * H2;    // [64][128]
    int tid = threadIdx.x;

    {
        const float4* src4 = reinterpret_cast<const float4*>(g_WW1);
        float4* dst4 = reinterpret_cast<float4*>(Bs);
        #pragma unroll
        for (int i = 0; i < 32; i++) dst4[tid + 256 * i] = src4[tid + 256 * i];
    }
    long row0 = (long)blockIdx.x * 64;
    {
        const float4* src4 = reinterpret_cast<const float4*>(g_S + row0 * IN_DIM);
        float4* dst4 = reinterpret_cast<float4*>(As);
        #pragma unroll
        for (int i = 0; i < 8; i++) dst4[tid + 256 * i] = src4[tid + 256 * i];
    }
    __syncthreads();

    int ty = tid >> 5, tx = tid & 31;
    unsigned long long acc[8][4];
    #pragma unroll
    for (int i = 0; i < 8; i++)
        #pragma unroll
        for (int j = 0; j < 4; j++) acc[i][j] = 0ULL;

    #pragma unroll 8
    for (int k = 0; k < IN_DIM; k++) {
        unsigned long long a2[8], b2[4];
        #pragma unroll
        for (int i = 0; i < 8; i++) {
            float a = As[(ty + 8 * i) * IN_DIM + k];   // warp-broadcast
            a2[i] = pack2(a, a);
        }
        #pragma unroll
        for (int j = 0; j < 4; j++)
            b2[j] = *reinterpret_cast<const unsigned long long*>(&Bs[k * H2 + 2 * tx + 64 * j]);
        #pragma unroll
        for (int i = 0; i < 8; i++)
            #pragma unroll
            for (int j = 0; j < 4; j++) fma2(acc[i][j], a2[i], b2[j]);
    }

    #pragma unroll
    for (int i = 0; i < 8; i++) {
        long r = row0 + ty + 8 * i;
        float dg = g_deg[r];
        #pragma unroll
        for (int j = 0; j < 4; j++) {
            int c = 2 * tx + 64 * j;
            float2 p = unpack2(acc[i][j]);
            float v0 = fmaxf(p.x + __ldg(b1 + c)     + dg * g_bvec1[c],     0.f);
            float v1 = fmaxf(p.y + __ldg(b1 + c + 1) + dg * g_bvec1[c + 1], 0.f);
            *reinterpret_cast<float2*>(&g_H1[r * H2 + c]) = make_float2(v0, v1);
        }
    }
}

// ---------------- GEMM2 + LN + relu + pool: per atom h_n, pooled into g_gsum_hn ----------------
// [M,256]x[256,128], block 64 rows, per-thread 8 rows x 2 col-pairs
__global__ __launch_bounds__(256) void gemm2_kernel(const float* __restrict__ w2,
                                                    const float* __restrict__ b2v,
                                                    const float* __restrict__ lng,
                                                    const float* __restrict__ lnb,
                                                    const int* __restrict__ gid,
                                                    int nAtoms) {
    extern __shared__ float sm[];
    float* Bs = sm;                 // [256][128]
    float* As = sm + H2 * HID;      // [64][256]
    int tid = threadIdx.x;

    {
        const float4* src4 = reinterpret_cast<const float4*>(w2);
        float4* dst4 = reinterpret_cast<float4*>(Bs);
        #pragma unroll
        for (int i = 0; i < 32; i++) dst4[tid + 256 * i] = src4[tid + 256 * i];
    }
    long row0 = (long)blockIdx.x * 64;
    {
        const float4* src4 = reinterpret_cast<const float4*>(g_H1 + row0 * H2);
        float4* dst4 = reinterpret_cast<float4*>(As);
        #pragma unroll
        for (int i = 0; i < 16; i++) dst4[tid + 256 * i] = src4[tid + 256 * i];
    }
    __syncthreads();

    int ty = tid >> 5, tx = tid & 31;
    unsigned long long acc[8][2];
    #pragma unroll
    for (int i = 0; i < 8; i++) { acc[i][0] = 0ULL; acc[i][1] = 0ULL; }

    #pragma unroll 8
    for (int k = 0; k < H2; k++) {
        unsigned long long a2[8], b2[2];
        #pragma unroll
        for (int i = 0; i < 8; i++) {
            float a = As[(ty + 8 * i) * H2 + k];
            a2[i] = pack2(a, a);
        }
        #pragma unroll
        for (int j = 0; j < 2; j++)
            b2[j] = *reinterpret_cast<const unsigned long long*>(&Bs[k * HID + 2 * tx + 64 * j]);
        #pragma unroll
        for (int i = 0; i < 8; i++) {
            fma2(acc[i][0], a2[i], b2[0]);
            fma2(acc[i][1], a2[i], b2[1]);
        }
    }

    // epilogue: +b2, layernorm over 128 (one row lives in one warp), relu, pool per graph
    #pragma unroll
    for (int i = 0; i < 8; i++) {
        long r = row0 + ty + 8 * i;
        float v[4];
        #pragma unroll
        for (int j = 0; j < 2; j++) {
            int c = 2 * tx + 64 * j;
            float2 p = unpack2(acc[i][j]);
            v[2 * j]     = p.x + __ldg(b2v + c);
            v[2 * j + 1] = p.y + __ldg(b2v + c + 1);
        }
        float s = v[0] + v[1] + v[2] + v[3];
        float q = v[0] * v[0] + v[1] * v[1] + v[2] * v[2] + v[3] * v[3];
        #pragma unroll
        for (int off = 16; off > 0; off >>= 1) {
            s += __shfl_xor_sync(0xffffffffu, s, off);
            q += __shfl_xor_sync(0xffffffffu, q, off);
        }
        float mean = s * (1.f / 128.f);
        float var  = q * (1.f / 128.f) - mean * mean;
        float rstd = rsqrtf(var + 1e-5f);
        if (r < nAtoms) {
            int g = __ldg(gid + r);
            float* base = g_gsum_hn + (long)g * HID;
            #pragma unroll
            for (int j = 0; j < 2; j++) {
                int c = 2 * tx + 64 * j;
                float y0 = fmaxf((v[2 * j]     - mean) * rstd * __ldg(lng + c)     + __ldg(lnb + c),     0.f);
                float y1 = fmaxf((v[2 * j + 1] - mean) * rstd * __ldg(lng + c + 1) + __ldg(lnb + c + 1), 0.f);
                red_add_v2(base + c, y0, y1);
            }
        }
    }
}

// ---------------- final: graph_repr = (gsum_nh @ W + cnt*b + gsum_hn) / max(cnt,1) ----------------
// [16384,128]x[128,128], block 64 rows, per-thread 8 rows x 2 col-pairs
__global__ __launch_bounds__(256) void final_kernel(const float* __restrict__ atom_w,
                                                    const float* __restrict__ atom_b,
                                                    float* __restrict__ out) {
    extern __shared__ float sm[];
    float* Bs = sm;                  // [128][128]
    float* As = sm + IN_DIM * HID;   // [64][128]
    int tid = threadIdx.x;

    {
        const float4* src4 = reinterpret_cast<const float4*>(atom_w);
        float4* dst4 = reinterpret_cast<float4*>(Bs);
        #pragma unroll
        for (int i = 0; i < 16; i++) dst4[tid + 256 * i] = src4[tid + 256 * i];
    }
    long row0 = (long)blockIdx.x * 64;
    {
        const float4* src4 = reinterpret_cast<const float4*>(g_gsum_nh + row0 * HID);
        float4* dst4 = reinterpret_cast<float4*>(As);
        #pragma unroll
        for (int i = 0; i < 8; i++) dst4[tid + 256 * i] = src4[tid + 256 * i];
    }
    __syncthreads();

    int ty = tid >> 5, tx = tid & 31;
    unsigned long long acc[8][2];
    #pragma unroll
    for (int i = 0; i < 8; i++) { acc[i][0] = 0ULL; acc[i][1] = 0ULL; }

    #pragma unroll 8
    for (int k = 0; k < IN_DIM; k++) {
        unsigned long long a2[8], b2[2];
        #pragma unroll
        for (int i = 0; i < 8; i++) {
            float a = As[(ty + 8 * i) * IN_DIM + k];
            a2[i] = pack2(a, a);
        }
        #pragma unroll
        for (int j = 0; j < 2; j++)
            b2[j] = *reinterpret_cast<const unsigned long long*>(&Bs[k * HID + 2 * tx + 64 * j]);
        #pragma unroll
        for (int i = 0; i < 8; i++) {
            fma2(acc[i][0], a2[i], b2[0]);
            fma2(acc[i][1], a2[i], b2[1]);
        }
    }

    #pragma unroll
    for (int i = 0; i < 8; i++) {
        long r = row0 + ty + 8 * i;
        float cn = g_cnt[r];
        float inv = 1.f / fmaxf(cn, 1.f);
        #pragma unroll
        for (int j = 0; j < 2; j++) {
            int c = 2 * tx + 64 * j;
            float2 p = unpack2(acc[i][j]);
            float o0 = (p.x + cn * __ldg(atom_b + c)     + g_gsum_hn[r * HID + c])     * inv;
            float o1 = (p.y + cn * __ldg(atom_b + c + 1) + g_gsum_hn[r * HID + c + 1]) * inv;
            *reinterpret_cast<float2*>(&out[r * HID + c]) = make_float2(o0, o1);
        }
    }
}

// ---------------- launch ----------------
extern "C" void kernel_launch(void* const* d_in, const int* in_sizes, int n_in,
                              void* d_out, int out_size) {
    const float* node_hidden = (const float*)d_in[0];
    const float* edge_hidden = (const float*)d_in[1];
    // d_in[2] angle_hidden: DEAD (edge_out deleted in reference)
    const float* atom_w  = (const float*)d_in[3];
    const float* atom_b  = (const float*)d_in[4];
    const float* nmlp_w1 = (const float*)d_in[5];
    const float* nmlp_b1 = (const float*)d_in[6];
    const float* nmlp_w2 = (const float*)d_in[7];
    const float* nmlp_b2 = (const float*)d_in[8];
    const float* n_ln_g  = (const float*)d_in[9];
    const float* n_ln_b  = (const float*)d_in[10];
    // d_in[11..16] edge MLP params: DEAD
    const int* ab_src = (const int*)d_in[17];
    const int* ab_dst = (const int*)d_in[18];
    // d_in[19], d_in[20] ba_src/ba_dst: DEAD
    const int* gid = (const int*)d_in[21];

    int nAtoms  = in_sizes[0] / IN_DIM;
    int nBonds  = in_sizes[1] / IN_DIM;
    int nGraphs = out_size / HID;

    cudaFuncSetAttribute(gemm1_kernel, cudaFuncAttributeMaxDynamicSharedMemorySize, (IN_DIM * H2 + 64 * IN_DIM) * 4);
    cudaFuncSetAttribute(gemm2_kernel, cudaFuncAttributeMaxDynamicSharedMemorySize, (H2 * HID + 64 * H2) * 4);
    cudaFuncSetAttribute(final_kernel, cudaFuncAttributeMaxDynamicSharedMemorySize, (IN_DIM * HID + 64 * IN_DIM) * 4);

    // 1. zero all accumulator scratch
    {
        long n4 = (long)MAX_ATOMS * IN_DIM / 4;
        int blocks = (int)((n4 + 255) / 256);
        zero_kernel<<<blocks, 256>>>();
    }
    // 2. fold weights: WW1 = atom_w @ nmlp_w1, bvec1 = 2 * atom_b @ nmlp_w1
    prep_kernel<<<IN_DIM + 1, 256>>>(atom_w, atom_b, nmlp_w1);
    // 3. scatter bonds into S (+degree)
    scatter_kernel<<<(nBonds * 32 + 255) / 256, 256>>>(
        (const float4*)node_hidden, (const float4*)edge_hidden, ab_src, ab_dst, nBonds);
    // 4. pool raw node_hidden per graph (+count)
    pool_nodes_kernel<<<(nAtoms * 32 + 255) / 256, 256>>>(
        (const float4*)node_hidden, gid, nAtoms);
    // 5. H1 = relu(S @ WW1 + b1 + deg*bvec1)
    int mblocks = (nAtoms + 63) / 64;
    gemm1_kernel<<<mblocks, 256, (IN_DIM * H2 + 64 * IN_DIM) * 4>>>(nmlp_b1);
    // 6. h_n = relu(LN(H1 @ W2 + b2)); pooled into g_gsum_hn
    gemm2_kernel<<<mblocks, 256, (H2 * HID + 64 * H2) * 4>>>(
        nmlp_w2, nmlp_b2, n_ln_g, n_ln_b, gid, nAtoms);
    // 7. graph_repr
    final_kernel<<<nGraphs / 64, 256, (IN_DIM * HID + 64 * IN_DIM) * 4>>>(
        atom_w, atom_b, (float*)d_out);
}

// round 5
// speedup vs baseline: 1.5939x; 1.5939x over previous
#include <cuda_runtime.h>
#include <cstdint>

// ---------------- constants ----------------
#define IN_DIM 128
#define HID 128
#define H2 256
#define MAX_ATOMS_PAD 500096   // 500000 padded to multiple of 128
#define MAX_GRAPHS 16384

// ---------------- scratch (device globals; no allocs allowed) ----------------
__device__ float g_S[(size_t)MAX_ATOMS_PAD * IN_DIM];   // segsum(node_hidden[src]+edge_hidden, dst)
__device__ float g_deg[MAX_ATOMS_PAD];                  // in-degree per atom
__device__ float g_gsum_nh[MAX_GRAPHS * HID];           // per-graph sum of node_hidden
__device__ float g_gsum_hn[MAX_GRAPHS * HID];           // per-graph sum of h_n
__device__ float g_cnt[MAX_GRAPHS];                     // atoms per graph
__device__ float g_H1[(size_t)MAX_ATOMS_PAD * H2];      // relu(first MLP layer)
__device__ float g_WW1t[H2 * IN_DIM];                   // (atom_w @ nmlp_w1)^T  [n][k], tf32-rounded
__device__ float g_W2t[HID * H2];                       // nmlp_w2^T             [n][k], tf32-rounded
__device__ float g_bvec1[H2];                           // 2 * atom_b @ nmlp_w1

// ---------------- small helpers ----------------
__device__ __forceinline__ uint32_t tf32r(float x) {
    uint32_t u; asm("cvt.rna.tf32.f32 %0, %1;" : "=r"(u) : "f"(x)); return u;
}
__device__ __forceinline__ void red_add_v4(float* p, float4 v) {
    asm volatile("red.global.add.v4.f32 [%0], {%1,%2,%3,%4};"
                 :: "l"(p), "f"(v.x), "f"(v.y), "f"(v.z), "f"(v.w) : "memory");
}
// f32x2 helpers (final_kernel)
__device__ __forceinline__ unsigned long long pack2(float lo, float hi) {
    unsigned long long r; asm("mov.b64 %0, {%1, %2};" : "=l"(r) : "f"(lo), "f"(hi)); return r;
}
__device__ __forceinline__ float2 unpack2(unsigned long long v) {
    float2 r; asm("mov.b64 {%0, %1}, %2;" : "=f"(r.x), "=f"(r.y) : "l"(v)); return r;
}
__device__ __forceinline__ void fma2(unsigned long long& d, unsigned long long a, unsigned long long b) {
    asm("fma.rn.f32x2 %0, %1, %2, %0;" : "+l"(d) : "l"(a), "l"(b));
}

// tf32 warp MMA: D(16x8) += A(16x8) * B(8x8), A row-major, B col-major
__device__ __forceinline__ void mma_tf32(float* c, const uint32_t* a, const uint32_t* b) {
    asm volatile(
        "mma.sync.aligned.m16n8k8.row.col.f32.tf32.tf32.f32 "
        "{%0,%1,%2,%3}, {%4,%5,%6,%7}, {%8,%9}, {%0,%1,%2,%3};"
        : "+f"(c[0]), "+f"(c[1]), "+f"(c[2]), "+f"(c[3])
        : "r"(a[0]), "r"(a[1]), "r"(a[2]), "r"(a[3]), "r"(b[0]), "r"(b[1]));
}

// ---------------- zero scratch ----------------
__global__ void zero_kernel() {
    long i = (long)blockIdx.x * blockDim.x + threadIdx.x;  // float4 index
    float4 z = make_float4(0.f, 0.f, 0.f, 0.f);
    const long nS = (long)MAX_ATOMS_PAD * IN_DIM / 4;
    if (i < nS) reinterpret_cast<float4*>(g_S)[i] = z;
    if (i < MAX_ATOMS_PAD / 4) reinterpret_cast<float4*>(g_deg)[i] = z;
    if (i < (long)MAX_GRAPHS * HID / 4) {
        reinterpret_cast<float4*>(g_gsum_nh)[i] = z;
        reinterpret_cast<float4*>(g_gsum_hn)[i] = z;
    }
    if (i < MAX_GRAPHS / 4) reinterpret_cast<float4*>(g_cnt)[i] = z;
}

// ---------------- prep: WW1t[n][k] = (atom_w@w1)^T (tf32), W2t[n][k] = w2^T (tf32), bvec1 ----------------
__global__ __launch_bounds__(256) void prep_kernel(const float* __restrict__ atom_w,
                                                   const float* __restrict__ atom_b,
                                                   const float* __restrict__ w1,
                                                   const float* __restrict__ w2) {
    int b = blockIdx.x, t = threadIdx.x;
    if (b < H2) {
        int n = b;
        if (t < IN_DIM) {
            float acc = 0.f;
            #pragma unroll 8
            for (int j = 0; j < IN_DIM; j++)
                acc += __ldg(atom_w + t * IN_DIM + j) * __ldg(w1 + j * H2 + n);
            g_WW1t[n * IN_DIM + t] = __uint_as_float(tf32r(acc));
        } else if (t == IN_DIM) {
            float acc = 0.f;
            for (int j = 0; j < IN_DIM; j++)
                acc += __ldg(atom_b + j) * __ldg(w1 + j * H2 + n);
            g_bvec1[n] = 2.f * acc;
        }
    } else {
        int n = b - H2;  // 0..127
        g_W2t[n * H2 + t] = __uint_as_float(tf32r(__ldg(w2 + t * HID + n)));
    }
}

// ---------------- scatter bonds: S[dst] += node_hidden[src] + edge_hidden ----------------
__global__ __launch_bounds__(256) void scatter_kernel(const float4* __restrict__ nh,
                                                      const float4* __restrict__ eh,
                                                      const int* __restrict__ src,
                                                      const int* __restrict__ dst,
                                                      int nBonds) {
    int t = blockIdx.x * 256 + threadIdx.x;
    int e = t >> 5, lane = t & 31;
    if (e >= nBonds) return;
    int s = __ldg(src + e), d = __ldg(dst + e);
    float4 a = __ldg(nh + (long)s * 32 + lane);
    float4 b = __ldg(eh + (long)e * 32 + lane);
    float4 v = make_float4(a.x + b.x, a.y + b.y, a.z + b.z, a.w + b.w);
    red_add_v4(g_S + (long)d * IN_DIM + lane * 4, v);
    if (lane == 0) atomicAdd(g_deg + d, 1.0f);
}

// ---------------- pool node_hidden per graph ----------------
__global__ __launch_bounds__(256) void pool_nodes_kernel(const float4* __restrict__ nh,
                                                         const int* __restrict__ gid,
                                                         int nAtoms) {
    int t = blockIdx.x * 256 + threadIdx.x;
    int a = t >> 5, lane = t & 31;
    if (a >= nAtoms) return;
    int g = __ldg(gid + a);
    float4 v = __ldg(nh + (long)a * 32 + lane);
    red_add_v4(g_gsum_nh + (long)g * HID + lane * 4, v);
    if (lane == 0) atomicAdd(g_cnt + g, 1.0f);
}

// ================= GEMM1 (mma.sync tf32): H1 = relu(S @ WW1 + b1 + deg*bvec1) =================
// CTA tile M=128, N=256, K=128. As [128][132], Bs(=WW1^T) [256][132], pad=4 floats.
#define G1_PAD 132
#define G1_SMEM_TOTAL ((128 * G1_PAD + 256 * G1_PAD) * 4)

__global__ __launch_bounds__(256) void gemm1_mma(const float* __restrict__ b1) {
    extern __shared__ float sm[];
    float* As = sm;                  // [128][132]
    float* Bs = sm + 128 * G1_PAD;   // [256][132]
    int tid = threadIdx.x, wid = tid >> 5, lane = tid & 31;
    int g = lane >> 2, tg = lane & 3;
    long row0 = (long)blockIdx.x * 128;

    // stage A (tf32-round)
    {
        const float4* Ag = reinterpret_cast<const float4*>(g_S + row0 * IN_DIM);
        #pragma unroll
        for (int i = 0; i < 16; i++) {
            int idx = tid + 256 * i;
            int r = idx >> 5, k4 = idx & 31;
            float4 v = __ldg(Ag + idx);
            uint4 u = make_uint4(tf32r(v.x), tf32r(v.y), tf32r(v.z), tf32r(v.w));
            *reinterpret_cast<uint4*>(&As[r * G1_PAD + k4 * 4]) = u;
        }
        const float4* Bg = reinterpret_cast<const float4*>(g_WW1t);
        #pragma unroll
        for (int i = 0; i < 32; i++) {
            int idx = tid + 256 * i;
            int n = idx >> 5, k4 = idx & 31;
            *reinterpret_cast<float4*>(&Bs[n * G1_PAD + k4 * 4]) = __ldg(Bg + idx);
        }
    }
    __syncthreads();

    int rm = (wid & 3) * 32;        // warp M offset
    int cn = (wid >> 2) * 128;      // warp N offset
    float acc[2][16][4];
    #pragma unroll
    for (int mf = 0; mf < 2; mf++)
        #pragma unroll
        for (int f = 0; f < 16; f++)
            #pragma unroll
            for (int j = 0; j < 4; j++) acc[mf][f][j] = 0.f;

    #pragma unroll 4
    for (int k0 = 0; k0 < 128; k0 += 8) {
        uint32_t a[2][4];
        #pragma unroll
        for (int mf = 0; mf < 2; mf++) {
            const float* ap = &As[(rm + mf * 16 + g) * G1_PAD + k0 + tg];
            a[mf][0] = __float_as_uint(ap[0]);
            a[mf][1] = __float_as_uint(ap[8 * G1_PAD]);
            a[mf][2] = __float_as_uint(ap[4]);
            a[mf][3] = __float_as_uint(ap[8 * G1_PAD + 4]);
        }
        #pragma unroll
        for (int f = 0; f < 16; f++) {
            const float* bp = &Bs[(cn + 8 * f + g) * G1_PAD + k0 + tg];
            uint32_t b[2] = { __float_as_uint(bp[0]), __float_as_uint(bp[4]) };
            mma_tf32(acc[0][f], a[0], b);
            mma_tf32(acc[1][f], a[1], b);
        }
    }

    // epilogue: bias + deg*bvec1 + relu -> g_H1
    #pragma unroll
    for (int mf = 0; mf < 2; mf++) {
        long r1 = row0 + rm + mf * 16 + g;
        long r2 = r1 + 8;
        float d1 = g_deg[r1], d2 = g_deg[r2];
        #pragma unroll
        for (int f = 0; f < 16; f++) {
            int c = cn + 8 * f + tg * 2;
            float bb0 = __ldg(b1 + c),     bv0 = g_bvec1[c];
            float bb1 = __ldg(b1 + c + 1), bv1 = g_bvec1[c + 1];
            float o0 = fmaxf(acc[mf][f][0] + bb0 + d1 * bv0, 0.f);
            float o1 = fmaxf(acc[mf][f][1] + bb1 + d1 * bv1, 0.f);
            float o2 = fmaxf(acc[mf][f][2] + bb0 + d2 * bv0, 0.f);
            float o3 = fmaxf(acc[mf][f][3] + bb1 + d2 * bv1, 0.f);
            *reinterpret_cast<float2*>(&g_H1[r1 * H2 + c]) = make_float2(o0, o1);
            *reinterpret_cast<float2*>(&g_H1[r2 * H2 + c]) = make_float2(o2, o3);
        }
    }
}

// ================= GEMM2 (mma.sync tf32): h_n = relu(LN(H1 @ W2 + b2)); pooled =================
// CTA tile M=128, N=128, K=256 in 2 chunks of 128. As/Bs [128][132] each chunk.
#define G2_PAD 132
#define G2_SMEM_TOTAL (2 * 128 * G2_PAD * 4)

__global__ __launch_bounds__(256) void gemm2_mma(const float* __restrict__ b2v,
                                                 const float* __restrict__ lng,
                                                 const float* __restrict__ lnb,
                                                 const int* __restrict__ gid,
                                                 int nAtoms) {
    extern __shared__ float sm[];
    float* As = sm;                  // [128][132]
    float* Bs = sm + 128 * G2_PAD;   // [128][132]
    int tid = threadIdx.x, wid = tid >> 5, lane = tid & 31;
    int g = lane >> 2, tg = lane & 3;
    long row0 = (long)blockIdx.x * 128;

    int rm = (wid & 3) * 32;
    int cn = (wid >> 2) * 64;
    float acc[2][8][4];
    #pragma unroll
    for (int mf = 0; mf < 2; mf++)
        #pragma unroll
        for (int f = 0; f < 8; f++)
            #pragma unroll
            for (int j = 0; j < 4; j++) acc[mf][f][j] = 0.f;

    for (int chunk = 0; chunk < 2; chunk++) {
        __syncthreads();   // previous chunk's LDS complete before restaging
        #pragma unroll
        for (int i = 0; i < 16; i++) {
            int idx = tid + 256 * i;
            int r = idx >> 5, k4 = idx & 31;
            float4 v = __ldg(reinterpret_cast<const float4*>(
                &g_H1[(row0 + r) * H2 + chunk * 128 + k4 * 4]));
            uint4 u = make_uint4(tf32r(v.x), tf32r(v.y), tf32r(v.z), tf32r(v.w));
            *reinterpret_cast<uint4*>(&As[r * G2_PAD + k4 * 4]) = u;
        }
        #pragma unroll
        for (int i = 0; i < 16; i++) {
            int idx = tid + 256 * i;
            int n = idx >> 5, k4 = idx & 31;
            *reinterpret_cast<float4*>(&Bs[n * G2_PAD + k4 * 4]) =
                __ldg(reinterpret_cast<const float4*>(&g_W2t[n * H2 + chunk * 128 + k4 * 4]));
        }
        __syncthreads();

        #pragma unroll 4
        for (int k0 = 0; k0 < 128; k0 += 8) {
            uint32_t a[2][4];
            #pragma unroll
            for (int mf = 0; mf < 2; mf++) {
                const float* ap = &As[(rm + mf * 16 + g) * G2_PAD + k0 + tg];
                a[mf][0] = __float_as_uint(ap[0]);
                a[mf][1] = __float_as_uint(ap[8 * G2_PAD]);
                a[mf][2] = __float_as_uint(ap[4]);
                a[mf][3] = __float_as_uint(ap[8 * G2_PAD + 4]);
            }
            #pragma unroll
            for (int f = 0; f < 8; f++) {
                const float* bp = &Bs[(cn + 8 * f + g) * G2_PAD + k0 + tg];
                uint32_t b[2] = { __float_as_uint(bp[0]), __float_as_uint(bp[4]) };
                mma_tf32(acc[0][f], a[0], b);
                mma_tf32(acc[1][f], a[1], b);
            }
        }
    }

    // write C tile to smem (reuse As region, stride 132), then per-row LN epilogue
    __syncthreads();
    float* Cs = sm;
    #pragma unroll
    for (int mf = 0; mf < 2; mf++) {
        int r1 = rm + mf * 16 + g;
        #pragma unroll
        for (int f = 0; f < 8; f++) {
            int c = cn + 8 * f + tg * 2;
            *reinterpret_cast<float2*>(&Cs[r1 * G2_PAD + c])       = make_float2(acc[mf][f][0], acc[mf][f][1]);
            *reinterpret_cast<float2*>(&Cs[(r1 + 8) * G2_PAD + c]) = make_float2(acc[mf][f][2], acc[mf][f][3]);
        }
    }
    __syncthreads();

    if (tid < 128) {
        long row = row0 + tid;
        if (row < nAtoms) {
            const float* crow = &Cs[tid * G2_PAD];
            float s = 0.f, q = 0.f;
            #pragma unroll
            for (int c = 0; c < 128; c++) {
                float x = crow[c] + __ldg(b2v + c);
                s += x; q += x * x;
            }
            float mean = s * (1.f / 128.f);
            float var  = q * (1.f / 128.f) - mean * mean;
            float rstd = rsqrtf(var + 1e-5f);
            int gr = __ldg(gid + row);
            float* base = g_gsum_hn + (long)gr * HID;
            #pragma unroll
            for (int j = 0; j < 32; j++) {
                int c = 4 * j;
                float4 y;
                y.x = fmaxf((crow[c + 0] + __ldg(b2v + c + 0) - mean) * rstd * __ldg(lng + c + 0) + __ldg(lnb + c + 0), 0.f);
                y.y = fmaxf((crow[c + 1] + __ldg(b2v + c + 1) - mean) * rstd * __ldg(lng + c + 1) + __ldg(lnb + c + 1), 0.f);
                y.z = fmaxf((crow[c + 2] + __ldg(b2v + c + 2) - mean) * rstd * __ldg(lng + c + 2) + __ldg(lnb + c + 2), 0.f);
                y.w = fmaxf((crow[c + 3] + __ldg(b2v + c + 3) - mean) * rstd * __ldg(lng + c + 3) + __ldg(lnb + c + 3), 0.f);
                red_add_v4(base + c, y);
            }
        }
    }
}

// ---------------- final: graph_repr = (gsum_nh @ W + cnt*b + gsum_hn) / max(cnt,1) ----------------
__global__ __launch_bounds__(256) void final_kernel(const float* __restrict__ atom_w,
                                                    const float* __restrict__ atom_b,
                                                    float* __restrict__ out) {
    extern __shared__ float sm[];
    float* Bs = sm;                  // [128][128]
    float* As = sm + IN_DIM * HID;   // [64][128]
    int tid = threadIdx.x;
    {
        const float4* src4 = reinterpret_cast<const float4*>(atom_w);
        float4* dst4 = reinterpret_cast<float4*>(Bs);
        #pragma unroll
        for (int i = 0; i < 16; i++) dst4[tid + 256 * i] = src4[tid + 256 * i];
    }
    long row0 = (long)blockIdx.x * 64;
    {
        const float4* src4 = reinterpret_cast<const float4*>(g_gsum_nh + row0 * HID);
        float4* dst4 = reinterpret_cast<float4*>(As);
        #pragma unroll
        for (int i = 0; i < 8; i++) dst4[tid + 256 * i] = src4[tid + 256 * i];
    }
    __syncthreads();

    int ty = tid >> 5, tx = tid & 31;
    unsigned long long acc[8][2];
    #pragma unroll
    for (int i = 0; i < 8; i++) { acc[i][0] = 0ULL; acc[i][1] = 0ULL; }

    #pragma unroll 8
    for (int k = 0; k < IN_DIM; k++) {
        unsigned long long a2[8], b2[2];
        #pragma unroll
        for (int i = 0; i < 8; i++) {
            float a = As[(ty + 8 * i) * IN_DIM + k];
            a2[i] = pack2(a, a);
        }
        #pragma unroll
        for (int j = 0; j < 2; j++)
            b2[j] = *reinterpret_cast<const unsigned long long*>(&Bs[k * HID + 2 * tx + 64 * j]);
        #pragma unroll
        for (int i = 0; i < 8; i++) { fma2(acc[i][0], a2[i], b2[0]); fma2(acc[i][1], a2[i], b2[1]); }
    }

    #pragma unroll
    for (int i = 0; i < 8; i++) {
        long r = row0 + ty + 8 * i;
        float cn = g_cnt[r];
        float inv = 1.f / fmaxf(cn, 1.f);
        #pragma unroll
        for (int j = 0; j < 2; j++) {
            int c = 2 * tx + 64 * j;
            float2 p = unpack2(acc[i][j]);
            float o0 = (p.x + cn * __ldg(atom_b + c)     + g_gsum_hn[r * HID + c])     * inv;
            float o1 = (p.y + cn * __ldg(atom_b + c + 1) + g_gsum_hn[r * HID + c + 1]) * inv;
            *reinterpret_cast<float2*>(&out[r * HID + c]) = make_float2(o0, o1);
        }
    }
}

// ---------------- launch ----------------
extern "C" void kernel_launch(void* const* d_in, const int* in_sizes, int n_in,
                              void* d_out, int out_size) {
    const float* node_hidden = (const float*)d_in[0];
    const float* edge_hidden = (const float*)d_in[1];
    // d_in[2] angle_hidden: DEAD (edge_out deleted in reference)
    const float* atom_w  = (const float*)d_in[3];
    const float* atom_b  = (const float*)d_in[4];
    const float* nmlp_w1 = (const float*)d_in[5];
    const float* nmlp_b1 = (const float*)d_in[6];
    const float* nmlp_w2 = (const float*)d_in[7];
    const float* nmlp_b2 = (const float*)d_in[8];
    const float* n_ln_g  = (const float*)d_in[9];
    const float* n_ln_b  = (const float*)d_in[10];
    // d_in[11..16] edge MLP params: DEAD
    const int* ab_src = (const int*)d_in[17];
    const int* ab_dst = (const int*)d_in[18];
    // d_in[19], d_in[20] ba_src/ba_dst: DEAD
    const int* gid = (const int*)d_in[21];

    int nAtoms  = in_sizes[0] / IN_DIM;
    int nBonds  = in_sizes[1] / IN_DIM;
    int nGraphs = out_size / HID;

    cudaFuncSetAttribute(gemm1_mma, cudaFuncAttributeMaxDynamicSharedMemorySize, G1_SMEM_TOTAL);
    cudaFuncSetAttribute(gemm2_mma, cudaFuncAttributeMaxDynamicSharedMemorySize, G2_SMEM_TOTAL);
    cudaFuncSetAttribute(final_kernel, cudaFuncAttributeMaxDynamicSharedMemorySize, (IN_DIM * HID + 64 * IN_DIM) * 4);

    // 1. zero accumulator scratch
    {
        long n4 = (long)MAX_ATOMS_PAD * IN_DIM / 4;
        int blocks = (int)((n4 + 255) / 256);
        zero_kernel<<<blocks, 256>>>();
    }
    // 2. fold + transpose weights (tf32-rounded)
    prep_kernel<<<H2 + HID, 256>>>(atom_w, atom_b, nmlp_w1, nmlp_w2);
    // 3. scatter bonds into S (+degree)
    scatter_kernel<<<(nBonds * 32 + 255) / 256, 256>>>(
        (const float4*)node_hidden, (const float4*)edge_hidden, ab_src, ab_dst, nBonds);
    // 4. pool raw node_hidden per graph (+count)
    pool_nodes_kernel<<<(nAtoms * 32 + 255) / 256, 256>>>(
        (const float4*)node_hidden, gid, nAtoms);
    // 5. H1 = relu(S @ WW1 + b1 + deg*bvec1)  (tf32 mma.sync)
    int mblocks = (nAtoms + 127) / 128;
    gemm1_mma<<<mblocks, 256, G1_SMEM_TOTAL>>>(nmlp_b1);
    // 6. h_n = relu(LN(H1 @ W2 + b2)); pooled into g_gsum_hn  (tf32 mma.sync)
    gemm2_mma<<<mblocks, 256, G2_SMEM_TOTAL>>>(nmlp_b2, n_ln_g, n_ln_b, gid, nAtoms);
    // 7. graph_repr
    final_kernel<<<nGraphs / 64, 256, (IN_DIM * HID + 64 * IN_DIM) * 4>>>(
        atom_w, atom_b, (float*)d_out);
}

// round 6
// speedup vs baseline: 1.9780x; 1.2410x over previous
#include <cuda_runtime.h>
#include <cstdint>

// ---------------- constants ----------------
#define IN_DIM 128
#define HID 128
#define H2 256
#define MAX_ATOMS_PAD 500096   // 500000 padded to multiple of 128
#define MAX_GRAPHS 16384

// ---------------- scratch (device globals; no allocs allowed) ----------------
__device__ float g_S[(size_t)MAX_ATOMS_PAD * IN_DIM];   // segsum(node_hidden[src]+edge_hidden, dst)
__device__ float g_deg[MAX_ATOMS_PAD];                  // in-degree per atom
__device__ float g_gsum_nh[MAX_GRAPHS * HID];           // per-graph sum of node_hidden
__device__ float g_gsum_hn[MAX_GRAPHS * HID];           // per-graph sum of h_n
__device__ float g_cnt[MAX_GRAPHS];                     // atoms per graph
__device__ float g_WW1t[H2 * IN_DIM];                   // (atom_w @ nmlp_w1)^T  [n][k], tf32-rounded
__device__ float g_W2t[HID * H2];                       // nmlp_w2^T             [n][k], tf32-rounded
__device__ float g_bvec1[H2];                           // 2 * atom_b @ nmlp_w1

// ---------------- small helpers ----------------
__device__ __forceinline__ uint32_t tf32r(float x) {
    uint32_t u; asm("cvt.rna.tf32.f32 %0, %1;" : "=r"(u) : "f"(x)); return u;
}
__device__ __forceinline__ void red_add_v4(float* p, float4 v) {
    asm volatile("red.global.add.v4.f32 [%0], {%1,%2,%3,%4};"
                 :: "l"(p), "f"(v.x), "f"(v.y), "f"(v.z), "f"(v.w) : "memory");
}
// f32x2 helpers (final_kernel)
__device__ __forceinline__ unsigned long long pack2(float lo, float hi) {
    unsigned long long r; asm("mov.b64 %0, {%1, %2};" : "=l"(r) : "f"(lo), "f"(hi)); return r;
}
__device__ __forceinline__ float2 unpack2(unsigned long long v) {
    float2 r; asm("mov.b64 {%0, %1}, %2;" : "=f"(r.x), "=f"(r.y) : "l"(v)); return r;
}
__device__ __forceinline__ void fma2(unsigned long long& d, unsigned long long a, unsigned long long b) {
    asm("fma.rn.f32x2 %0, %1, %2, %0;" : "+l"(d) : "l"(a), "l"(b));
}

// tf32 warp MMA: D(16x8) += A(16x8) * B(8x8), A row-major, B col-major
__device__ __forceinline__ void mma_tf32(float* c, const uint32_t* a, const uint32_t* b) {
    asm volatile(
        "mma.sync.aligned.m16n8k8.row.col.f32.tf32.tf32.f32 "
        "{%0,%1,%2,%3}, {%4,%5,%6,%7}, {%8,%9}, {%0,%1,%2,%3};"
        : "+f"(c[0]), "+f"(c[1]), "+f"(c[2]), "+f"(c[3])
        : "r"(a[0]), "r"(a[1]), "r"(a[2]), "r"(a[3]), "r"(b[0]), "r"(b[1]));
}

// ---------------- zero scratch ----------------
__global__ void zero_kernel() {
    long i = (long)blockIdx.x * blockDim.x + threadIdx.x;  // float4 index
    float4 z = make_float4(0.f, 0.f, 0.f, 0.f);
    const long nS = (long)MAX_ATOMS_PAD * IN_DIM / 4;
    if (i < nS) reinterpret_cast<float4*>(g_S)[i] = z;
    if (i < MAX_ATOMS_PAD / 4) reinterpret_cast<float4*>(g_deg)[i] = z;
    if (i < (long)MAX_GRAPHS * HID / 4) {
        reinterpret_cast<float4*>(g_gsum_nh)[i] = z;
        reinterpret_cast<float4*>(g_gsum_hn)[i] = z;
    }
    if (i < MAX_GRAPHS / 4) reinterpret_cast<float4*>(g_cnt)[i] = z;
}

// ---------------- prep: WW1t[n][k] = (atom_w@w1)^T (tf32), W2t[n][k] = w2^T (tf32), bvec1 ----------------
__global__ __launch_bounds__(256) void prep_kernel(const float* __restrict__ atom_w,
                                                   const float* __restrict__ atom_b,
                                                   const float* __restrict__ w1,
                                                   const float* __restrict__ w2) {
    int b = blockIdx.x, t = threadIdx.x;
    if (b < H2) {
        int n = b;
        if (t < IN_DIM) {
            float acc = 0.f;
            #pragma unroll 8
            for (int j = 0; j < IN_DIM; j++)
                acc += __ldg(atom_w + t * IN_DIM + j) * __ldg(w1 + j * H2 + n);
            g_WW1t[n * IN_DIM + t] = __uint_as_float(tf32r(acc));
        } else if (t == IN_DIM) {
            float acc = 0.f;
            for (int j = 0; j < IN_DIM; j++)
                acc += __ldg(atom_b + j) * __ldg(w1 + j * H2 + n);
            g_bvec1[n] = 2.f * acc;
        }
    } else {
        int n = b - H2;  // 0..127
        g_W2t[n * H2 + t] = __uint_as_float(tf32r(__ldg(w2 + t * HID + n)));
    }
}

// ---------------- scatter bonds: S[dst] += node_hidden[src] + edge_hidden ----------------
__global__ __launch_bounds__(256) void scatter_kernel(const float4* __restrict__ nh,
                                                      const float4* __restrict__ eh,
                                                      const int* __restrict__ src,
                                                      const int* __restrict__ dst,
                                                      int nBonds) {
    int t = blockIdx.x * 256 + threadIdx.x;
    int e = t >> 5, lane = t & 31;
    if (e >= nBonds) return;
    int s = __ldg(src + e), d = __ldg(dst + e);
    float4 a = __ldg(nh + (long)s * 32 + lane);
    float4 b = __ldg(eh + (long)e * 32 + lane);
    float4 v = make_float4(a.x + b.x, a.y + b.y, a.z + b.z, a.w + b.w);
    red_add_v4(g_S + (long)d * IN_DIM + lane * 4, v);
    if (lane == 0) atomicAdd(g_deg + d, 1.0f);
}

// ---------------- pool node_hidden per graph ----------------
__global__ __launch_bounds__(256) void pool_nodes_kernel(const float4* __restrict__ nh,
                                                         const int* __restrict__ gid,
                                                         int nAtoms) {
    int t = blockIdx.x * 256 + threadIdx.x;
    int a = t >> 5, lane = t & 31;
    if (a >= nAtoms) return;
    int g = __ldg(gid + a);
    float4 v = __ldg(nh + (long)a * 32 + lane);
    red_add_v4(g_gsum_nh + (long)g * HID + lane * 4, v);
    if (lane == 0) atomicAdd(g_cnt + g, 1.0f);
}

// ================= FUSED MLP (mma.sync tf32):
//   H1 = relu(S @ WW1 + b1 + deg*bvec1)   [smem-resident, never hits DRAM]
//   h_n = relu(LN(H1 @ W2 + b2))          -> pooled per graph into g_gsum_hn
// CTA tile M=128. Three smem regions of [128][132] floats:
//   R0 = As (S tile)      -> later H1 chunk-1 (k 128..255)
//   R1 = Bs (weights)     -> later C tile for LN epilogue
//   R2 = H1 chunk-0 (k 0..127)
#define PADW 132
#define FUSED_SMEM_TOTAL (3 * 128 * PADW * 4)

__global__ __launch_bounds__(256) void fused_mlp(const float* __restrict__ b1,
                                                 const float* __restrict__ b2v,
                                                 const float* __restrict__ lng,
                                                 const float* __restrict__ lnb,
                                                 const int* __restrict__ gid,
                                                 int nAtoms) {
    extern __shared__ float sm[];
    float* R0 = sm;                   // As, then H1 chunk1
    float* R1 = sm + 128 * PADW;      // Bs, then C tile
    float* R2 = sm + 2 * 128 * PADW;  // H1 chunk0
    int tid = threadIdx.x, wid = tid >> 5, lane = tid & 31;
    int g = lane >> 2, tg = lane & 3;
    long row0 = (long)blockIdx.x * 128;

    int rm = (wid & 3) * 32;        // warp M offset
    int cnw = (wid >> 2) * 64;      // warp N offset within 128-col chunk

    // ---- stage A = tf32(S tile) into R0 ----
    {
        const float4* Ag = reinterpret_cast<const float4*>(g_S + row0 * IN_DIM);
        #pragma unroll
        for (int i = 0; i < 16; i++) {
            int idx = tid + 256 * i;
            int r = idx >> 5, k4 = idx & 31;
            float4 v = __ldg(Ag + idx);
            uint4 u = make_uint4(tf32r(v.x), tf32r(v.y), tf32r(v.z), tf32r(v.w));
            *reinterpret_cast<uint4*>(&R0[r * PADW + k4 * 4]) = u;
        }
    }

    // ---- GEMM1 in two N=128 chunks ----
    #pragma unroll
    for (int c = 0; c < 2; c++) {
        if (c == 1) __syncthreads();   // chunk0 mma reads of R1 done
        // load Bs = WW1t rows [c*128, c*128+128)
        {
            const float4* Bg = reinterpret_cast<const float4*>(g_WW1t + (long)c * 128 * IN_DIM);
            #pragma unroll
            for (int i = 0; i < 16; i++) {
                int idx = tid + 256 * i;
                int n = idx >> 5, k4 = idx & 31;
                *reinterpret_cast<float4*>(&R1[n * PADW + k4 * 4]) = __ldg(Bg + idx);
            }
        }
        __syncthreads();

        float acc[2][8][4];
        #pragma unroll
        for (int mf = 0; mf < 2; mf++)
            #pragma unroll
            for (int f = 0; f < 8; f++)
                #pragma unroll
                for (int j = 0; j < 4; j++) acc[mf][f][j] = 0.f;

        #pragma unroll 4
        for (int k0 = 0; k0 < 128; k0 += 8) {
            uint32_t a[2][4];
            #pragma unroll
            for (int mf = 0; mf < 2; mf++) {
                const float* ap = &R0[(rm + mf * 16 + g) * PADW + k0 + tg];
                a[mf][0] = __float_as_uint(ap[0]);
                a[mf][1] = __float_as_uint(ap[8 * PADW]);
                a[mf][2] = __float_as_uint(ap[4]);
                a[mf][3] = __float_as_uint(ap[8 * PADW + 4]);
            }
            #pragma unroll
            for (int f = 0; f < 8; f++) {
                const float* bp = &R1[(cnw + 8 * f + g) * PADW + k0 + tg];
                uint32_t b[2] = { __float_as_uint(bp[0]), __float_as_uint(bp[4]) };
                mma_tf32(acc[0][f], a[0], b);
                mma_tf32(acc[1][f], a[1], b);
            }
        }

        // chunk1 epilogue overwrites R0 (As) — all warps must finish mma first
        if (c == 1) __syncthreads();
        float* Hd = (c == 0) ? R2 : R0;
        #pragma unroll
        for (int mf = 0; mf < 2; mf++) {
            int r1 = rm + mf * 16 + g;
            float d1 = g_deg[row0 + r1], d2 = g_deg[row0 + r1 + 8];
            #pragma unroll
            for (int f = 0; f < 8; f++) {
                int lc = cnw + 8 * f + tg * 2;     // local col within chunk
                int gc = c * 128 + lc;             // global H1 col
                float bb0 = __ldg(b1 + gc),     bv0 = g_bvec1[gc];
                float bb1 = __ldg(b1 + gc + 1), bv1 = g_bvec1[gc + 1];
                uint2 o1, o2;
                o1.x = tf32r(fmaxf(acc[mf][f][0] + bb0 + d1 * bv0, 0.f));
                o1.y = tf32r(fmaxf(acc[mf][f][1] + bb1 + d1 * bv1, 0.f));
                o2.x = tf32r(fmaxf(acc[mf][f][2] + bb0 + d2 * bv0, 0.f));
                o2.y = tf32r(fmaxf(acc[mf][f][3] + bb1 + d2 * bv1, 0.f));
                *reinterpret_cast<uint2*>(&Hd[r1 * PADW + lc])       = o1;
                *reinterpret_cast<uint2*>(&Hd[(r1 + 8) * PADW + lc]) = o2;
            }
        }
    }

    // ---- GEMM2: C = H1 @ W2, K=256 in two chunks (A = R2 then R0) ----
    __syncthreads();   // H1 writes visible; gemm1 use of R1 done
    float acc2[2][8][4];
    #pragma unroll
    for (int mf = 0; mf < 2; mf++)
        #pragma unroll
        for (int f = 0; f < 8; f++)
            #pragma unroll
            for (int j = 0; j < 4; j++) acc2[mf][f][j] = 0.f;

    #pragma unroll
    for (int c = 0; c < 2; c++) {
        if (c == 1) __syncthreads();   // chunk0 mma reads of R1 done
        // load Bs = W2t[n][c*128 + k]
        #pragma unroll
        for (int i = 0; i < 16; i++) {
            int idx = tid + 256 * i;
            int n = idx >> 5, k4 = idx & 31;
            *reinterpret_cast<float4*>(&R1[n * PADW + k4 * 4]) =
                __ldg(reinterpret_cast<const float4*>(&g_W2t[n * H2 + c * 128 + k4 * 4]));
        }
        __syncthreads();

        const float* Ah = (c == 0) ? R2 : R0;
        #pragma unroll 4
        for (int k0 = 0; k0 < 128; k0 += 8) {
            uint32_t a[2][4];
            #pragma unroll
            for (int mf = 0; mf < 2; mf++) {
                const float* ap = &Ah[(rm + mf * 16 + g) * PADW + k0 + tg];
                a[mf][0] = __float_as_uint(ap[0]);
                a[mf][1] = __float_as_uint(ap[8 * PADW]);
                a[mf][2] = __float_as_uint(ap[4]);
                a[mf][3] = __float_as_uint(ap[8 * PADW + 4]);
            }
            #pragma unroll
            for (int f = 0; f < 8; f++) {
                const float* bp = &R1[(cnw + 8 * f + g) * PADW + k0 + tg];
                uint32_t b[2] = { __float_as_uint(bp[0]), __float_as_uint(bp[4]) };
                mma_tf32(acc2[0][f], a[0], b);
                mma_tf32(acc2[1][f], a[1], b);
            }
        }
    }

    // ---- C tile into R1 (Bs dead), then per-row LN + relu + graph pool ----
    __syncthreads();
    #pragma unroll
    for (int mf = 0; mf < 2; mf++) {
        int r1 = rm + mf * 16 + g;
        #pragma unroll
        for (int f = 0; f < 8; f++) {
            int cc = cnw + 8 * f + tg * 2;
            *reinterpret_cast<float2*>(&R1[r1 * PADW + cc])       = make_float2(acc2[mf][f][0], acc2[mf][f][1]);
            *reinterpret_cast<float2*>(&R1[(r1 + 8) * PADW + cc]) = make_float2(acc2[mf][f][2], acc2[mf][f][3]);
        }
    }
    __syncthreads();

    if (tid < 128) {
        long row = row0 + tid;
        if (row < nAtoms) {
            const float* crow = &R1[tid * PADW];
            float s = 0.f, q = 0.f;
            #pragma unroll
            for (int j = 0; j < 32; j++) {
                float4 x4 = *reinterpret_cast<const float4*>(&crow[4 * j]);
                float4 b4 = *reinterpret_cast<const float4*>(b2v + 4 * j);
                float x0 = x4.x + b4.x, x1 = x4.y + b4.y, x2 = x4.z + b4.z, x3 = x4.w + b4.w;
                s += x0 + x1 + x2 + x3;
                q += x0 * x0 + x1 * x1 + x2 * x2 + x3 * x3;
            }
            float mean = s * (1.f / 128.f);
            float var  = q * (1.f / 128.f) - mean * mean;
            float rstd = rsqrtf(var + 1e-5f);
            int gr = __ldg(gid + row);
            float* base = g_gsum_hn + (long)gr * HID;
            #pragma unroll
            for (int j = 0; j < 32; j++) {
                int c = 4 * j;
                float4 x4 = *reinterpret_cast<const float4*>(&crow[c]);
                float4 b4 = *reinterpret_cast<const float4*>(b2v + c);
                float4 g4 = *reinterpret_cast<const float4*>(lng + c);
                float4 l4 = *reinterpret_cast<const float4*>(lnb + c);
                float4 y;
                y.x = fmaxf((x4.x + b4.x - mean) * rstd * g4.x + l4.x, 0.f);
                y.y = fmaxf((x4.y + b4.y - mean) * rstd * g4.y + l4.y, 0.f);
                y.z = fmaxf((x4.z + b4.z - mean) * rstd * g4.z + l4.z, 0.f);
                y.w = fmaxf((x4.w + b4.w - mean) * rstd * g4.w + l4.w, 0.f);
                red_add_v4(base + c, y);
            }
        }
    }
}

// ---------------- final: graph_repr = (gsum_nh @ W + cnt*b + gsum_hn) / max(cnt,1) ----------------
__global__ __launch_bounds__(256) void final_kernel(const float* __restrict__ atom_w,
                                                    const float* __restrict__ atom_b,
                                                    float* __restrict__ out) {
    extern __shared__ float sm[];
    float* Bs = sm;                  // [128][128]
    float* As = sm + IN_DIM * HID;   // [64][128]
    int tid = threadIdx.x;
    {
        const float4* src4 = reinterpret_cast<const float4*>(atom_w);
        float4* dst4 = reinterpret_cast<float4*>(Bs);
        #pragma unroll
        for (int i = 0; i < 16; i++) dst4[tid + 256 * i] = src4[tid + 256 * i];
    }
    long row0 = (long)blockIdx.x * 64;
    {
        const float4* src4 = reinterpret_cast<const float4*>(g_gsum_nh + row0 * HID);
        float4* dst4 = reinterpret_cast<float4*>(As);
        #pragma unroll
        for (int i = 0; i < 8; i++) dst4[tid + 256 * i] = src4[tid + 256 * i];
    }
    __syncthreads();

    int ty = tid >> 5, tx = tid & 31;
    unsigned long long acc[8][2];
    #pragma unroll
    for (int i = 0; i < 8; i++) { acc[i][0] = 0ULL; acc[i][1] = 0ULL; }

    #pragma unroll 8
    for (int k = 0; k < IN_DIM; k++) {
        unsigned long long a2[8], b2[2];
        #pragma unroll
        for (int i = 0; i < 8; i++) {
            float a = As[(ty + 8 * i) * IN_DIM + k];
            a2[i] = pack2(a, a);
        }
        #pragma unroll
        for (int j = 0; j < 2; j++)
            b2[j] = *reinterpret_cast<const unsigned long long*>(&Bs[k * HID + 2 * tx + 64 * j]);
        #pragma unroll
        for (int i = 0; i < 8; i++) { fma2(acc[i][0], a2[i], b2[0]); fma2(acc[i][1], a2[i], b2[1]); }
    }

    #pragma unroll
    for (int i = 0; i < 8; i++) {
        long r = row0 + ty + 8 * i;
        float cn = g_cnt[r];
        float inv = 1.f / fmaxf(cn, 1.f);
        #pragma unroll
        for (int j = 0; j < 2; j++) {
            int c = 2 * tx + 64 * j;
            float2 p = unpack2(acc[i][j]);
            float o0 = (p.x + cn * __ldg(atom_b + c)     + g_gsum_hn[r * HID + c])     * inv;
            float o1 = (p.y + cn * __ldg(atom_b + c + 1) + g_gsum_hn[r * HID + c + 1]) * inv;
            *reinterpret_cast<float2*>(&out[r * HID + c]) = make_float2(o0, o1);
        }
    }
}

// ---------------- launch ----------------
extern "C" void kernel_launch(void* const* d_in, const int* in_sizes, int n_in,
                              void* d_out, int out_size) {
    const float* node_hidden = (const float*)d_in[0];
    const float* edge_hidden = (const float*)d_in[1];
    // d_in[2] angle_hidden: DEAD (edge_out deleted in reference)
    const float* atom_w  = (const float*)d_in[3];
    const float* atom_b  = (const float*)d_in[4];
    const float* nmlp_w1 = (const float*)d_in[5];
    const float* nmlp_b1 = (const float*)d_in[6];
    const float* nmlp_w2 = (const float*)d_in[7];
    const float* nmlp_b2 = (const float*)d_in[8];
    const float* n_ln_g  = (const float*)d_in[9];
    const float* n_ln_b  = (const float*)d_in[10];
    // d_in[11..16] edge MLP params: DEAD
    const int* ab_src = (const int*)d_in[17];
    const int* ab_dst = (const int*)d_in[18];
    // d_in[19], d_in[20] ba_src/ba_dst: DEAD
    const int* gid = (const int*)d_in[21];

    int nAtoms  = in_sizes[0] / IN_DIM;
    int nBonds  = in_sizes[1] / IN_DIM;
    int nGraphs = out_size / HID;

    cudaFuncSetAttribute(fused_mlp, cudaFuncAttributeMaxDynamicSharedMemorySize, FUSED_SMEM_TOTAL);
    cudaFuncSetAttribute(final_kernel, cudaFuncAttributeMaxDynamicSharedMemorySize, (IN_DIM * HID + 64 * IN_DIM) * 4);

    // 1. zero accumulator scratch
    {
        long n4 = (long)MAX_ATOMS_PAD * IN_DIM / 4;
        int blocks = (int)((n4 + 255) / 256);
        zero_kernel<<<blocks, 256>>>();
    }
    // 2. fold + transpose weights (tf32-rounded)
    prep_kernel<<<H2 + HID, 256>>>(atom_w, atom_b, nmlp_w1, nmlp_w2);
    // 3. scatter bonds into S (+degree)
    scatter_kernel<<<(nBonds * 32 + 255) / 256, 256>>>(
        (const float4*)node_hidden, (const float4*)edge_hidden, ab_src, ab_dst, nBonds);
    // 4. pool raw node_hidden per graph (+count)
    pool_nodes_kernel<<<(nAtoms * 32 + 255) / 256, 256>>>(
        (const float4*)node_hidden, gid, nAtoms);
    // 5+6 fused: H1 in smem; h_n = relu(LN(H1@W2+b2)) pooled into g_gsum_hn
    int mblocks = (nAtoms + 127) / 128;
    fused_mlp<<<mblocks, 256, FUSED_SMEM_TOTAL>>>(nmlp_b1, nmlp_b2, n_ln_g, n_ln_b, gid, nAtoms);
    // 7. graph_repr
    final_kernel<<<nGraphs / 64, 256, (IN_DIM * HID + 64 * IN_DIM) * 4>>>(
        atom_w, atom_b, (float*)d_out);
}

// round 7
// speedup vs baseline: 2.1544x; 1.0892x over previous
#include <cuda_runtime.h>
#include <cstdint>

// ---------------- constants ----------------
#define IN_DIM 128
#define HID 128
#define H2 256
#define MAX_ATOMS_PAD 500096   // 500000 padded to multiple of 128
#define MAX_GRAPHS 16384

// ---------------- scratch (device globals; no allocs allowed) ----------------
__device__ float g_S[(size_t)MAX_ATOMS_PAD * IN_DIM];   // segsum(node_hidden[src]+edge_hidden, dst)
__device__ float g_deg[MAX_ATOMS_PAD];                  // in-degree per atom
__device__ float g_gsum_nh[MAX_GRAPHS * HID];           // per-graph sum of node_hidden
__device__ float g_gsum_hn[MAX_GRAPHS * HID];           // per-graph sum of h_n
__device__ float g_cnt[MAX_GRAPHS];                     // atoms per graph
__device__ float g_WW1t[H2 * IN_DIM];                   // (atom_w @ nmlp_w1)^T  [n][k], tf32-rounded
__device__ float g_W2t[HID * H2];                       // nmlp_w2^T             [n][k], tf32-rounded
__device__ float g_bvec1[H2];                           // 2 * atom_b @ nmlp_w1

// ---------------- small helpers ----------------
__device__ __forceinline__ uint32_t tf32r(float x) {
    uint32_t u; asm("cvt.rna.tf32.f32 %0, %1;" : "=r"(u) : "f"(x)); return u;
}
__device__ __forceinline__ void red_add_v4(float* p, float4 v) {
    asm volatile("red.global.add.v4.f32 [%0], {%1,%2,%3,%4};"
                 :: "l"(p), "f"(v.x), "f"(v.y), "f"(v.z), "f"(v.w) : "memory");
}
__device__ __forceinline__ void red_add_f32(float* p, float v) {
    asm volatile("red.global.add.f32 [%0], %1;" :: "l"(p), "f"(v) : "memory");
}
// f32x2 helpers (final_kernel)
__device__ __forceinline__ unsigned long long pack2(float lo, float hi) {
    unsigned long long r; asm("mov.b64 %0, {%1, %2};" : "=l"(r) : "f"(lo), "f"(hi)); return r;
}
__device__ __forceinline__ float2 unpack2(unsigned long long v) {
    float2 r; asm("mov.b64 {%0, %1}, %2;" : "=f"(r.x), "=f"(r.y) : "l"(v)); return r;
}
__device__ __forceinline__ void fma2(unsigned long long& d, unsigned long long a, unsigned long long b) {
    asm("fma.rn.f32x2 %0, %1, %2, %0;" : "+l"(d) : "l"(a), "l"(b));
}

// tf32 warp MMA: D(16x8) += A(16x8) * B(8x8), A row-major, B col-major
__device__ __forceinline__ void mma_tf32(float* c, const uint32_t* a, const uint32_t* b) {
    asm volatile(
        "mma.sync.aligned.m16n8k8.row.col.f32.tf32.tf32.f32 "
        "{%0,%1,%2,%3}, {%4,%5,%6,%7}, {%8,%9}, {%0,%1,%2,%3};"
        : "+f"(c[0]), "+f"(c[1]), "+f"(c[2]), "+f"(c[3])
        : "r"(a[0]), "r"(a[1]), "r"(a[2]), "r"(a[3]), "r"(b[0]), "r"(b[1]));
}

// ---------------- zero scratch ----------------
__global__ void zero_kernel() {
    long i = (long)blockIdx.x * blockDim.x + threadIdx.x;  // float4 index
    float4 z = make_float4(0.f, 0.f, 0.f, 0.f);
    const long nS = (long)MAX_ATOMS_PAD * IN_DIM / 4;
    if (i < nS) reinterpret_cast<float4*>(g_S)[i] = z;
    if (i < MAX_ATOMS_PAD / 4) reinterpret_cast<float4*>(g_deg)[i] = z;
    if (i < (long)MAX_GRAPHS * HID / 4) {
        reinterpret_cast<float4*>(g_gsum_nh)[i] = z;
        reinterpret_cast<float4*>(g_gsum_hn)[i] = z;
    }
    if (i < MAX_GRAPHS / 4) reinterpret_cast<float4*>(g_cnt)[i] = z;
}

// ---------------- prep: WW1t[n][k] = (atom_w@w1)^T (tf32), W2t[n][k] = w2^T (tf32), bvec1 ----------------
__global__ __launch_bounds__(256) void prep_kernel(const float* __restrict__ atom_w,
                                                   const float* __restrict__ atom_b,
                                                   const float* __restrict__ w1,
                                                   const float* __restrict__ w2) {
    int b = blockIdx.x, t = threadIdx.x;
    if (b < H2) {
        int n = b;
        if (t < IN_DIM) {
            float acc = 0.f;
            #pragma unroll 8
            for (int j = 0; j < IN_DIM; j++)
                acc += __ldg(atom_w + t * IN_DIM + j) * __ldg(w1 + j * H2 + n);
            g_WW1t[n * IN_DIM + t] = __uint_as_float(tf32r(acc));
        } else if (t == IN_DIM) {
            float acc = 0.f;
            for (int j = 0; j < IN_DIM; j++)
                acc += __ldg(atom_b + j) * __ldg(w1 + j * H2 + n);
            g_bvec1[n] = 2.f * acc;
        }
    } else {
        int n = b - H2;  // 0..127
        g_W2t[n * H2 + t] = __uint_as_float(tf32r(__ldg(w2 + t * HID + n)));
    }
}

// ---------------- scatter bonds: S[dst] += node_hidden[src] + edge_hidden ----------------
__global__ __launch_bounds__(256) void scatter_kernel(const float4* __restrict__ nh,
                                                      const float4* __restrict__ eh,
                                                      const int* __restrict__ src,
                                                      const int* __restrict__ dst,
                                                      int nBonds) {
    int t = blockIdx.x * 256 + threadIdx.x;
    int e = t >> 5, lane = t & 31;
    if (e >= nBonds) return;
    int s = __ldg(src + e), d = __ldg(dst + e);
    float4 a = __ldg(nh + (long)s * 32 + lane);
    float4 b = __ldg(eh + (long)e * 32 + lane);
    float4 v = make_float4(a.x + b.x, a.y + b.y, a.z + b.z, a.w + b.w);
    red_add_v4(g_S + (long)d * IN_DIM + lane * 4, v);
    if (lane == 0) atomicAdd(g_deg + d, 1.0f);
}

// ---------------- pool node_hidden per graph: segmented (gid is SORTED) ----------------
// Block covers PCH contiguous atoms. Warp = one stream (strided by 8 atoms),
// lanes = 32 float4 column groups. Registers accumulate per graph run; one
// red.v4 per run boundary instead of per atom (~20x fewer atomics).
#define PCH 512
__global__ __launch_bounds__(256) void pool_nodes_seg(const float4* __restrict__ nh,
                                                      const int* __restrict__ gid,
                                                      int nAtoms) {
    int lane = threadIdx.x & 31;   // column group
    int p = threadIdx.x >> 5;      // stream 0..7
    int a0 = blockIdx.x * PCH;
    int aend = min(a0 + PCH, nAtoms);
    float4 acc = make_float4(0.f, 0.f, 0.f, 0.f);
    float cnt = 0.f;
    int cur = -1;
    for (int a = a0 + p; a < aend; a += 8) {
        int g = __ldg(gid + a);
        if (g != cur) {
            if (cur >= 0) {
                red_add_v4(g_gsum_nh + (long)cur * HID + lane * 4, acc);
                if (lane == 0) red_add_f32(g_cnt + cur, cnt);
            }
            acc = make_float4(0.f, 0.f, 0.f, 0.f); cnt = 0.f; cur = g;
        }
        float4 v = __ldg(nh + (long)a * 32 + lane);
        acc.x += v.x; acc.y += v.y; acc.z += v.z; acc.w += v.w;
        cnt += 1.f;
    }
    if (cur >= 0) {
        red_add_v4(g_gsum_nh + (long)cur * HID + lane * 4, acc);
        if (lane == 0) red_add_f32(g_cnt + cur, cnt);
    }
}

// ================= FUSED MLP (mma.sync tf32):
//   H1 = relu(S @ WW1 + b1 + deg*bvec1)   [smem-resident, never hits DRAM]
//   h_n = relu(LN(H1 @ W2 + b2))          -> pooled per graph into g_gsum_hn
// CTA tile M=128. Three smem regions of [128][132] floats:
//   R0 = As (S tile)      -> later H1 chunk-1 (k 128..255) -> gid cache
//   R1 = Bs (weights)     -> later C tile / LN output for segmented pooling
//   R2 = H1 chunk-0 (k 0..127)
#define PADW 132
#define FUSED_SMEM_TOTAL (3 * 128 * PADW * 4)

__global__ __launch_bounds__(256) void fused_mlp(const float* __restrict__ b1,
                                                 const float* __restrict__ b2v,
                                                 const float* __restrict__ lng,
                                                 const float* __restrict__ lnb,
                                                 const int* __restrict__ gid,
                                                 int nAtoms) {
    extern __shared__ float sm[];
    float* R0 = sm;                   // As, then H1 chunk1
    float* R1 = sm + 128 * PADW;      // Bs, then C tile
    float* R2 = sm + 2 * 128 * PADW;  // H1 chunk0
    int tid = threadIdx.x, wid = tid >> 5, lane = tid & 31;
    int g = lane >> 2, tg = lane & 3;
    long row0 = (long)blockIdx.x * 128;

    int rm = (wid & 3) * 32;        // warp M offset
    int cnw = (wid >> 2) * 64;      // warp N offset within 128-col chunk

    // ---- stage A = tf32(S tile) into R0 ----
    {
        const float4* Ag = reinterpret_cast<const float4*>(g_S + row0 * IN_DIM);
        #pragma unroll
        for (int i = 0; i < 16; i++) {
            int idx = tid + 256 * i;
            int r = idx >> 5, k4 = idx & 31;
            float4 v = __ldg(Ag + idx);
            uint4 u = make_uint4(tf32r(v.x), tf32r(v.y), tf32r(v.z), tf32r(v.w));
            *reinterpret_cast<uint4*>(&R0[r * PADW + k4 * 4]) = u;
        }
    }

    // ---- GEMM1 in two N=128 chunks ----
    #pragma unroll
    for (int c = 0; c < 2; c++) {
        if (c == 1) __syncthreads();   // chunk0 mma reads of R1 done
        // load Bs = WW1t rows [c*128, c*128+128)
        {
            const float4* Bg = reinterpret_cast<const float4*>(g_WW1t + (long)c * 128 * IN_DIM);
            #pragma unroll
            for (int i = 0; i < 16; i++) {
                int idx = tid + 256 * i;
                int n = idx >> 5, k4 = idx & 31;
                *reinterpret_cast<float4*>(&R1[n * PADW + k4 * 4]) = __ldg(Bg + idx);
            }
        }
        __syncthreads();

        float acc[2][8][4];
        #pragma unroll
        for (int mf = 0; mf < 2; mf++)
            #pragma unroll
            for (int f = 0; f < 8; f++)
                #pragma unroll
                for (int j = 0; j < 4; j++) acc[mf][f][j] = 0.f;

        #pragma unroll 8
        for (int k0 = 0; k0 < 128; k0 += 8) {
            uint32_t a[2][4];
            #pragma unroll
            for (int mf = 0; mf < 2; mf++) {
                const float* ap = &R0[(rm + mf * 16 + g) * PADW + k0 + tg];
                a[mf][0] = __float_as_uint(ap[0]);
                a[mf][1] = __float_as_uint(ap[8 * PADW]);
                a[mf][2] = __float_as_uint(ap[4]);
                a[mf][3] = __float_as_uint(ap[8 * PADW + 4]);
            }
            #pragma unroll
            for (int f = 0; f < 8; f++) {
                const float* bp = &R1[(cnw + 8 * f + g) * PADW + k0 + tg];
                uint32_t b[2] = { __float_as_uint(bp[0]), __float_as_uint(bp[4]) };
                mma_tf32(acc[0][f], a[0], b);
                mma_tf32(acc[1][f], a[1], b);
            }
        }

        // chunk1 epilogue overwrites R0 (As) — all warps must finish mma first
        if (c == 1) __syncthreads();
        float* Hd = (c == 0) ? R2 : R0;
        #pragma unroll
        for (int mf = 0; mf < 2; mf++) {
            int r1 = rm + mf * 16 + g;
            float d1 = g_deg[row0 + r1], d2 = g_deg[row0 + r1 + 8];
            #pragma unroll
            for (int f = 0; f < 8; f++) {
                int lc = cnw + 8 * f + tg * 2;     // local col within chunk
                int gc = c * 128 + lc;             // global H1 col
                float bb0 = __ldg(b1 + gc),     bv0 = g_bvec1[gc];
                float bb1 = __ldg(b1 + gc + 1), bv1 = g_bvec1[gc + 1];
                uint2 o1, o2;
                o1.x = tf32r(fmaxf(acc[mf][f][0] + bb0 + d1 * bv0, 0.f));
                o1.y = tf32r(fmaxf(acc[mf][f][1] + bb1 + d1 * bv1, 0.f));
                o2.x = tf32r(fmaxf(acc[mf][f][2] + bb0 + d2 * bv0, 0.f));
                o2.y = tf32r(fmaxf(acc[mf][f][3] + bb1 + d2 * bv1, 0.f));
                *reinterpret_cast<uint2*>(&Hd[r1 * PADW + lc])       = o1;
                *reinterpret_cast<uint2*>(&Hd[(r1 + 8) * PADW + lc]) = o2;
            }
        }
    }

    // ---- GEMM2: C = H1 @ W2, K=256 in two chunks (A = R2 then R0) ----
    __syncthreads();   // H1 writes visible; gemm1 use of R1 done
    float acc2[2][8][4];
    #pragma unroll
    for (int mf = 0; mf < 2; mf++)
        #pragma unroll
        for (int f = 0; f < 8; f++)
            #pragma unroll
            for (int j = 0; j < 4; j++) acc2[mf][f][j] = 0.f;

    #pragma unroll
    for (int c = 0; c < 2; c++) {
        if (c == 1) __syncthreads();   // chunk0 mma reads of R1 done
        // load Bs = W2t[n][c*128 + k]
        #pragma unroll
        for (int i = 0; i < 16; i++) {
            int idx = tid + 256 * i;
            int n = idx >> 5, k4 = idx & 31;
            *reinterpret_cast<float4*>(&R1[n * PADW + k4 * 4]) =
                __ldg(reinterpret_cast<const float4*>(&g_W2t[n * H2 + c * 128 + k4 * 4]));
        }
        __syncthreads();

        const float* Ah = (c == 0) ? R2 : R0;
        #pragma unroll 8
        for (int k0 = 0; k0 < 128; k0 += 8) {
            uint32_t a[2][4];
            #pragma unroll
            for (int mf = 0; mf < 2; mf++) {
                const float* ap = &Ah[(rm + mf * 16 + g) * PADW + k0 + tg];
                a[mf][0] = __float_as_uint(ap[0]);
                a[mf][1] = __float_as_uint(ap[8 * PADW]);
                a[mf][2] = __float_as_uint(ap[4]);
                a[mf][3] = __float_as_uint(ap[8 * PADW + 4]);
            }
            #pragma unroll
            for (int f = 0; f < 8; f++) {
                const float* bp = &R1[(cnw + 8 * f + g) * PADW + k0 + tg];
                uint32_t b[2] = { __float_as_uint(bp[0]), __float_as_uint(bp[4]) };
                mma_tf32(acc2[0][f], a[0], b);
                mma_tf32(acc2[1][f], a[1], b);
            }
        }
    }

    // ---- C tile into R1 (Bs dead) ----
    __syncthreads();
    #pragma unroll
    for (int mf = 0; mf < 2; mf++) {
        int r1 = rm + mf * 16 + g;
        #pragma unroll
        for (int f = 0; f < 8; f++) {
            int cc = cnw + 8 * f + tg * 2;
            *reinterpret_cast<float2*>(&R1[r1 * PADW + cc])       = make_float2(acc2[mf][f][0], acc2[mf][f][1]);
            *reinterpret_cast<float2*>(&R1[(r1 + 8) * PADW + cc]) = make_float2(acc2[mf][f][2], acc2[mf][f][3]);
        }
    }
    __syncthreads();

    // ---- per-row LN + relu, y written back into R1; cache gid in R0 ----
    int* gids = reinterpret_cast<int*>(R0);
    if (tid < 128) {
        long row = row0 + tid;
        gids[tid] = (row < nAtoms) ? __ldg(gid + row) : -1;
        float* crow = &R1[tid * PADW];
        float s = 0.f, q = 0.f;
        #pragma unroll
        for (int j = 0; j < 32; j++) {
            float4 x4 = *reinterpret_cast<const float4*>(&crow[4 * j]);
            float4 b4 = *reinterpret_cast<const float4*>(b2v + 4 * j);
            float x0 = x4.x + b4.x, x1 = x4.y + b4.y, x2 = x4.z + b4.z, x3 = x4.w + b4.w;
            s += x0 + x1 + x2 + x3;
            q += x0 * x0 + x1 * x1 + x2 * x2 + x3 * x3;
        }
        float mean = s * (1.f / 128.f);
        float var  = q * (1.f / 128.f) - mean * mean;
        float rstd = rsqrtf(var + 1e-5f);
        #pragma unroll
        for (int j = 0; j < 32; j++) {
            int c = 4 * j;
            float4 x4 = *reinterpret_cast<const float4*>(&crow[c]);
            float4 b4 = *reinterpret_cast<const float4*>(b2v + c);
            float4 g4 = *reinterpret_cast<const float4*>(lng + c);
            float4 l4 = *reinterpret_cast<const float4*>(lnb + c);
            float4 y;
            y.x = fmaxf((x4.x + b4.x - mean) * rstd * g4.x + l4.x, 0.f);
            y.y = fmaxf((x4.y + b4.y - mean) * rstd * g4.y + l4.y, 0.f);
            y.z = fmaxf((x4.z + b4.z - mean) * rstd * g4.z + l4.z, 0.f);
            y.w = fmaxf((x4.w + b4.w - mean) * rstd * g4.w + l4.w, 0.f);
            *reinterpret_cast<float4*>(&crow[c]) = y;
        }
    }
    __syncthreads();

    // ---- segmented pool over sorted rows: thread = (col, half), scan 64 rows,
    //      flush one scalar red per graph run (gid sorted -> ~4 runs per tile) ----
    {
        int c = tid & 127, half = tid >> 7;
        int rbeg = half * 64, rend = rbeg + 64;
        float acc = 0.f; int cur = -1;
        for (int r = rbeg; r < rend; r++) {
            int gr = gids[r];
            if (gr != cur) {
                if (cur >= 0) red_add_f32(g_gsum_hn + (long)cur * HID + c, acc);
                acc = 0.f; cur = gr;
            }
            if (gr >= 0) acc += R1[r * PADW + c];
        }
        if (cur >= 0) red_add_f32(g_gsum_hn + (long)cur * HID + c, acc);
    }
}

// ---------------- final: graph_repr = (gsum_nh @ W + cnt*b + gsum_hn) / max(cnt,1) ----------------
__global__ __launch_bounds__(256) void final_kernel(const float* __restrict__ atom_w,
                                                    const float* __restrict__ atom_b,
                                                    float* __restrict__ out) {
    extern __shared__ float sm[];
    float* Bs = sm;                  // [128][128]
    float* As = sm + IN_DIM * HID;   // [64][128]
    int tid = threadIdx.x;
    {
        const float4* src4 = reinterpret_cast<const float4*>(atom_w);
        float4* dst4 = reinterpret_cast<float4*>(Bs);
        #pragma unroll
        for (int i = 0; i < 16; i++) dst4[tid + 256 * i] = src4[tid + 256 * i];
    }
    long row0 = (long)blockIdx.x * 64;
    {
        const float4* src4 = reinterpret_cast<const float4*>(g_gsum_nh + row0 * HID);
        float4* dst4 = reinterpret_cast<float4*>(As);
        #pragma unroll
        for (int i = 0; i < 8; i++) dst4[tid + 256 * i] = src4[tid + 256 * i];
    }
    __syncthreads();

    int ty = tid >> 5, tx = tid & 31;
    unsigned long long acc[8][2];
    #pragma unroll
    for (int i = 0; i < 8; i++) { acc[i][0] = 0ULL; acc[i][1] = 0ULL; }

    #pragma unroll 8
    for (int k = 0; k < IN_DIM; k++) {
        unsigned long long a2[8], b2[2];
        #pragma unroll
        for (int i = 0; i < 8; i++) {
            float a = As[(ty + 8 * i) * IN_DIM + k];
            a2[i] = pack2(a, a);
        }
        #pragma unroll
        for (int j = 0; j < 2; j++)
            b2[j] = *reinterpret_cast<const unsigned long long*>(&Bs[k * HID + 2 * tx + 64 * j]);
        #pragma unroll
        for (int i = 0; i < 8; i++) { fma2(acc[i][0], a2[i], b2[0]); fma2(acc[i][1], a2[i], b2[1]); }
    }

    #pragma unroll
    for (int i = 0; i < 8; i++) {
        long r = row0 + ty + 8 * i;
        float cn = g_cnt[r];
        float inv = 1.f / fmaxf(cn, 1.f);
        #pragma unroll
        for (int j = 0; j < 2; j++) {
            int c = 2 * tx + 64 * j;
            float2 p = unpack2(acc[i][j]);
            float o0 = (p.x + cn * __ldg(atom_b + c)     + g_gsum_hn[r * HID + c])     * inv;
            float o1 = (p.y + cn * __ldg(atom_b + c + 1) + g_gsum_hn[r * HID + c + 1]) * inv;
            *reinterpret_cast<float2*>(&out[r * HID + c]) = make_float2(o0, o1);
        }
    }
}

// ---------------- launch ----------------
extern "C" void kernel_launch(void* const* d_in, const int* in_sizes, int n_in,
                              void* d_out, int out_size) {
    const float* node_hidden = (const float*)d_in[0];
    const float* edge_hidden = (const float*)d_in[1];
    // d_in[2] angle_hidden: DEAD (edge_out deleted in reference)
    const float* atom_w  = (const float*)d_in[3];
    const float* atom_b  = (const float*)d_in[4];
    const float* nmlp_w1 = (const float*)d_in[5];
    const float* nmlp_b1 = (const float*)d_in[6];
    const float* nmlp_w2 = (const float*)d_in[7];
    const float* nmlp_b2 = (const float*)d_in[8];
    const float* n_ln_g  = (const float*)d_in[9];
    const float* n_ln_b  = (const float*)d_in[10];
    // d_in[11..16] edge MLP params: DEAD
    const int* ab_src = (const int*)d_in[17];
    const int* ab_dst = (const int*)d_in[18];
    // d_in[19], d_in[20] ba_src/ba_dst: DEAD
    const int* gid = (const int*)d_in[21];

    int nAtoms  = in_sizes[0] / IN_DIM;
    int nBonds  = in_sizes[1] / IN_DIM;
    int nGraphs = out_size / HID;

    cudaFuncSetAttribute(fused_mlp, cudaFuncAttributeMaxDynamicSharedMemorySize, FUSED_SMEM_TOTAL);
    cudaFuncSetAttribute(final_kernel, cudaFuncAttributeMaxDynamicSharedMemorySize, (IN_DIM * HID + 64 * IN_DIM) * 4);

    // 1. zero accumulator scratch
    {
        long n4 = (long)MAX_ATOMS_PAD * IN_DIM / 4;
        int blocks = (int)((n4 + 255) / 256);
        zero_kernel<<<blocks, 256>>>();
    }
    // 2. fold + transpose weights (tf32-rounded)
    prep_kernel<<<H2 + HID, 256>>>(atom_w, atom_b, nmlp_w1, nmlp_w2);
    // 3. scatter bonds into S (+degree)
    scatter_kernel<<<(nBonds * 32 + 255) / 256, 256>>>(
        (const float4*)node_hidden, (const float4*)edge_hidden, ab_src, ab_dst, nBonds);
    // 4. pool raw node_hidden per graph, segmented over sorted gid (+count)
    pool_nodes_seg<<<(nAtoms + PCH - 1) / PCH, 256>>>(
        (const float4*)node_hidden, gid, nAtoms);
    // 5+6 fused: H1 in smem; h_n = relu(LN(H1@W2+b2)) pooled into g_gsum_hn
    int mblocks = (nAtoms + 127) / 128;
    fused_mlp<<<mblocks, 256, FUSED_SMEM_TOTAL>>>(nmlp_b1, nmlp_b2, n_ln_g, n_ln_b, gid, nAtoms);
    // 7. graph_repr
    final_kernel<<<nGraphs / 64, 256, (IN_DIM * HID + 64 * IN_DIM) * 4>>>(
        atom_w, atom_b, (float*)d_out);
}